// round 2
// baseline (speedup 1.0000x reference)
#include <cuda_runtime.h>

// ---------------------------------------------------------------------------
// SLAYER SRM-alpha SNN forward pass, t-major internal layout [t*N + n].
// Each layer kernel fuses: spatial op (pool/conv/fc) + psp filter + spike scan.
// ---------------------------------------------------------------------------

#define T_STEPS 300

// ---- scratch (device globals: no cudaMalloc allowed) ----------------------
__device__ float g_s0[16384  * T_STEPS];   // pool0 out -> spikes (B,2,32,32)
__device__ float g_s1[131072 * T_STEPS];   // conv1 spikes (B,16,32,32)
__device__ float g_s2[32768  * T_STEPS];   // pool1 spikes (B,16,16,16)
__device__ float g_s3[65536  * T_STEPS];   // conv2 spikes (B,32,16,16)
__device__ float g_s4[16384  * T_STEPS];   // pool2 spikes (B,32,8,8)
__device__ float g_u5[4096   * T_STEPS];   // fc1 potentials -> spikes in place
__device__ float g_u6[88     * T_STEPS];   // fc2 potentials

// ---- SRM constants (f32 rounded from the same doubles JAX casts) ----------
struct Srm { float p1, q1, p2, q2; };

__device__ __forceinline__ float srm_step(Srm& s, float u) {
    const float D  = 0.36787944117144233f;   // exp(-Ts/tau)
    const float CE = 2.7182818284590452f;    // e*Ts/tau
    const float CR = -54.365636569180905f;   // -2*theta*e
    // psp: q = d*(q+p); p = d*p + u; y = c*q   (explicit rn ops: no contraction)
    s.q1 = __fmul_rn(D, __fadd_rn(s.q1, s.p1));
    s.p1 = __fadd_rn(__fmul_rn(D, s.p1), u);
    float y = __fmul_rn(CE, s.q1);
    // spike: q = d*(q+p); s = (y + cr*q >= theta); p = d*p + s
    s.q2 = __fmul_rn(D, __fadd_rn(s.q2, s.p2));
    float sp = (__fadd_rn(y, __fmul_rn(CR, s.q2)) >= 10.0f) ? 1.0f : 0.0f;
    s.p2 = __fadd_rn(__fmul_rn(D, s.p2), sp);
    return sp;
}

// ---------------------------------------------------------------------------
// K0: 4x4 sum-pool (gain 11.0) + transpose (B,2,128,128,T) -> t-major g_s0.
// Reads coalesced along t, writes coalesced along n via smem transpose tile.
// ---------------------------------------------------------------------------
__global__ void pool0_transpose_kernel(const float* __restrict__ x) {
    __shared__ float sm[32][33];
    const int tx = threadIdx.x;           // t within 32-tile
    const int ty = threadIdx.y;           // 0..7
    const int tb = blockIdx.x;            // t-block 0..9
    const int nb = blockIdx.y;            // (b,c,ho) 0..511
    const int t  = tb * 32 + tx;
    const int ho = nb & 31;
    const int bc = nb >> 5;               // b*2 + c
    for (int j = ty; j < 32; j += 8) {    // j = wo
        float acc = 0.f;
        if (t < T_STEPS) {
            #pragma unroll
            for (int dy = 0; dy < 4; ++dy) {
                int h = ho * 4 + dy;
                const float* rowp = x + ((bc * 128 + h) * 128 + j * 4) * T_STEPS + t;
                acc += rowp[0] + rowp[300] + rowp[600] + rowp[900];
            }
        }
        sm[j][tx] = 11.0f * acc;          // exact: integer count * 11
    }
    __syncthreads();
    for (int jj = ty; jj < 32; jj += 8) {
        int t2 = tb * 32 + jj;
        if (t2 < T_STEPS)
            g_s0[t2 * 16384 + nb * 32 + tx] = sm[tx][jj];
    }
}

// ---- generic scan body (in-place psp+spike over t) -------------------------
__device__ __forceinline__ void scan_body(float* buf, int N) {
    int n = blockIdx.x * blockDim.x + threadIdx.x;
    if (n >= N) return;
    Srm st = {0.f, 0.f, 0.f, 0.f};
    #pragma unroll 1
    for (int t = 0; t < T_STEPS; ++t) {
        float u = buf[t * N + n];
        buf[t * N + n] = srm_step(st, u);
    }
}
__global__ void scan_s0_kernel() { scan_body(g_s0, 16384); }
__global__ void scan_u5_kernel() { scan_body(g_u5, 4096); }

// ---------------------------------------------------------------------------
// conv1 (5x5, pad2, 2->16ch, 32x32) fused with psp+spike.
// Block = (y,b): 256 thr = 8 co-pairs x 32 x. Weights in registers (2x50).
// ---------------------------------------------------------------------------
__global__ void __launch_bounds__(256) conv1_scan_kernel(const float* __restrict__ W1) {
    __shared__ float sin_[2][5][36];
    const int tid = threadIdx.x;
    const int x   = tid & 31;
    const int co0 = (tid >> 5) * 2;
    const int y   = blockIdx.x;           // 0..31
    const int b   = blockIdx.y;           // 0..7
    float w0[50], w1[50];
    #pragma unroll
    for (int k = 0; k < 50; ++k) {
        w0[k] = W1[co0 * 50 + k];
        w1[k] = W1[(co0 + 1) * 50 + k];
    }
    Srm st0 = {0.f,0.f,0.f,0.f}, st1 = {0.f,0.f,0.f,0.f};
    const int inBase  = (b * 2) * 1024;
    const int outIdx0 = ((b * 16 + co0) * 32 + y) * 32 + x;
    #pragma unroll 1
    for (int t = 0; t < T_STEPS; ++t) {
        const float* frame = g_s0 + t * 16384;
        for (int i = tid; i < 360; i += 256) {
            int ci = i / 180, rem = i % 180, r = rem / 36, xx = rem % 36;
            int row = y + r - 2, col = xx - 2;
            float v = 0.f;
            if (row >= 0 && row < 32 && col >= 0 && col < 32)
                v = frame[inBase + ci * 1024 + row * 32 + col];
            sin_[ci][r][xx] = v;
        }
        __syncthreads();
        float a0 = 0.f, a1 = 0.f;
        #pragma unroll
        for (int ci = 0; ci < 2; ++ci)
            #pragma unroll
            for (int ky = 0; ky < 5; ++ky)
                #pragma unroll
                for (int kx = 0; kx < 5; ++kx) {
                    float v = sin_[ci][ky][x + kx];
                    int k = ci * 25 + ky * 5 + kx;
                    a0 = fmaf(v, w0[k], a0);
                    a1 = fmaf(v, w1[k], a1);
                }
        float* out = g_s1 + t * 131072;
        out[outIdx0]        = srm_step(st0, a0);
        out[outIdx0 + 1024] = srm_step(st1, a1);
        __syncthreads();
    }
}

// ---------------------------------------------------------------------------
// pool1 (2x2, gain 11) + scan : g_s1 (B,16,32,32) -> g_s2 (B,16,16,16)
// ---------------------------------------------------------------------------
__global__ void pool1_scan_kernel() {
    int n = blockIdx.x * 256 + threadIdx.x;   // 32768 neurons
    int wo = n & 15, ho = (n >> 4) & 15, bc = n >> 8;  // bc = b*16+c
    int base = (bc * 32 + 2 * ho) * 32 + 2 * wo;
    Srm st = {0.f, 0.f, 0.f, 0.f};
    #pragma unroll 1
    for (int t = 0; t < T_STEPS; ++t) {
        const float* f = g_s1 + t * 131072;
        float2 r0 = *(const float2*)(f + base);
        float2 r1 = *(const float2*)(f + base + 32);
        float u = 11.0f * ((r0.x + r0.y) + (r1.x + r1.y));  // exact
        g_s2[t * 32768 + n] = srm_step(st, u);
    }
}

// ---------------------------------------------------------------------------
// conv2 (3x3, pad1, 16->32ch, 16x16) fused with psp+spike.
// Block = (y,b): 128 thr = 32 co x 4 x-groups (4 pixels each). Weights in regs.
// ---------------------------------------------------------------------------
__global__ void __launch_bounds__(128) conv2_scan_kernel(const float* __restrict__ W2) {
    __shared__ float sin_[16][3][18];
    const int tid = threadIdx.x;
    const int x0  = (tid & 3) * 4;
    const int co  = tid >> 2;             // 0..31
    const int y   = blockIdx.x;           // 0..15
    const int b   = blockIdx.y;
    float w[144];
    #pragma unroll
    for (int k = 0; k < 144; ++k) w[k] = W2[co * 144 + k];
    Srm st[4] = {{0,0,0,0},{0,0,0,0},{0,0,0,0},{0,0,0,0}};
    const int inBase  = (b * 16) * 256;
    const int outBase = ((b * 32 + co) * 16 + y) * 16 + x0;
    #pragma unroll 1
    for (int t = 0; t < T_STEPS; ++t) {
        const float* frame = g_s2 + t * 32768;
        for (int i = tid; i < 864; i += 128) {
            int ci = i / 54, rem = i % 54, r = rem / 18, xx = rem % 18;
            int row = y + r - 1, col = xx - 1;
            float v = 0.f;
            if (row >= 0 && row < 16 && col >= 0 && col < 16)
                v = frame[inBase + ci * 256 + row * 16 + col];
            sin_[ci][r][xx] = v;
        }
        __syncthreads();
        float a0 = 0.f, a1 = 0.f, a2 = 0.f, a3 = 0.f;
        #pragma unroll
        for (int ci = 0; ci < 16; ++ci)
            #pragma unroll
            for (int ky = 0; ky < 3; ++ky) {
                float v0 = sin_[ci][ky][x0 + 0], v1 = sin_[ci][ky][x0 + 1];
                float v2 = sin_[ci][ky][x0 + 2], v3 = sin_[ci][ky][x0 + 3];
                float v4 = sin_[ci][ky][x0 + 4], v5 = sin_[ci][ky][x0 + 5];
                float k0 = w[ci * 9 + ky * 3 + 0];
                float k1 = w[ci * 9 + ky * 3 + 1];
                float k2 = w[ci * 9 + ky * 3 + 2];
                a0 = fmaf(v0, k0, fmaf(v1, k1, fmaf(v2, k2, a0)));
                a1 = fmaf(v1, k0, fmaf(v2, k1, fmaf(v3, k2, a1)));
                a2 = fmaf(v2, k0, fmaf(v3, k1, fmaf(v4, k2, a2)));
                a3 = fmaf(v3, k0, fmaf(v4, k1, fmaf(v5, k2, a3)));
            }
        float4 sv;
        sv.x = srm_step(st[0], a0);
        sv.y = srm_step(st[1], a1);
        sv.z = srm_step(st[2], a2);
        sv.w = srm_step(st[3], a3);
        *(float4*)(g_s3 + t * 65536 + outBase) = sv;
        __syncthreads();
    }
}

// ---------------------------------------------------------------------------
// pool2 (2x2, gain 11) + scan : g_s3 (B,32,16,16) -> g_s4 (B,32,8,8)
// ---------------------------------------------------------------------------
__global__ void pool2_scan_kernel() {
    int n = blockIdx.x * 256 + threadIdx.x;   // 16384 neurons
    int wo = n & 7, ho = (n >> 3) & 7, bc = n >> 6;    // bc = b*32+c
    int base = (bc * 16 + 2 * ho) * 16 + 2 * wo;
    Srm st = {0.f, 0.f, 0.f, 0.f};
    #pragma unroll 1
    for (int t = 0; t < T_STEPS; ++t) {
        const float* f = g_s3 + t * 65536;
        float2 r0 = *(const float2*)(f + base);
        float2 r1 = *(const float2*)(f + base + 16);
        float u = 11.0f * ((r0.x + r0.y) + (r1.x + r1.y));
        g_s4[t * 16384 + n] = srm_step(st, u);
    }
}

// ---------------------------------------------------------------------------
// fc1 GEMM: rows = (t,b) pairs (2400), K=2048, N=512.
// A row r is contiguous: g_s4 + r*2048. 128x64 tile, 8x4 micro, kc=32.
// ---------------------------------------------------------------------------
__global__ void __launch_bounds__(256) fc1_gemm_kernel(const float* __restrict__ Wf1) {
    __shared__ float As[32 * 129];
    __shared__ float Bs[32 * 65];
    const int tid = threadIdx.x;
    const int txn = tid & 15, tym = tid >> 4;
    const int m0 = blockIdx.x * 128;
    const int n0 = blockIdx.y * 64;
    float acc[8][4];
    #pragma unroll
    for (int i = 0; i < 8; ++i)
        #pragma unroll
        for (int j = 0; j < 4; ++j) acc[i][j] = 0.f;

    for (int kb = 0; kb < 2048; kb += 32) {
        #pragma unroll
        for (int e = 0; e < 16; ++e) {                // A: 128x32
            int lin = tid + e * 256;
            int m = lin >> 5, k = lin & 31;
            int row = m0 + m;
            As[k * 129 + m] = (row < 2400) ? g_s4[row * 2048 + kb + k] : 0.f;
        }
        #pragma unroll
        for (int e = 0; e < 8; ++e) {                 // B: 64x32
            int lin = tid + e * 256;
            int nn = lin >> 5, k = lin & 31;
            Bs[k * 65 + nn] = Wf1[(n0 + nn) * 2048 + kb + k];
        }
        __syncthreads();
        #pragma unroll
        for (int k = 0; k < 32; ++k) {
            float a[8], bb[4];
            #pragma unroll
            for (int i = 0; i < 8; ++i) a[i] = As[k * 129 + tym * 8 + i];
            #pragma unroll
            for (int j = 0; j < 4; ++j) bb[j] = Bs[k * 65 + txn * 4 + j];
            #pragma unroll
            for (int i = 0; i < 8; ++i)
                #pragma unroll
                for (int j = 0; j < 4; ++j)
                    acc[i][j] = fmaf(a[i], bb[j], acc[i][j]);
        }
        __syncthreads();
    }
    #pragma unroll
    for (int i = 0; i < 8; ++i) {
        int row = m0 + tym * 8 + i;
        if (row < 2400) {
            float4 v = make_float4(acc[i][0], acc[i][1], acc[i][2], acc[i][3]);
            *(float4*)(g_u5 + row * 512 + n0 + txn * 4) = v;
        }
    }
}

// ---------------------------------------------------------------------------
// fc2: (row,o) dot over 512 spikes; row*11+o == t*88 + (b*11+o)  (t-major ok)
// ---------------------------------------------------------------------------
__global__ void fc2_kernel(const float* __restrict__ Wf2) {
    int idx = blockIdx.x * 256 + threadIdx.x;
    if (idx >= 2400 * 11) return;
    int row = idx / 11, o = idx % 11;
    const float* a  = g_u5 + row * 512;   // spikes (scan done in place)
    const float* wv = Wf2 + o * 512;
    float acc = 0.f;
    #pragma unroll 8
    for (int c = 0; c < 512; ++c) acc = fmaf(a[c], wv[c], acc);
    g_u6[idx] = acc;
}

// final scan: g_u6 [t*88+n] -> out[(b*11+o)*300 + t]
__global__ void final_scan_kernel(float* __restrict__ out) {
    int n = threadIdx.x;
    if (n >= 88) return;
    Srm st = {0.f, 0.f, 0.f, 0.f};
    #pragma unroll 1
    for (int t = 0; t < T_STEPS; ++t) {
        float s = srm_step(st, g_u6[t * 88 + n]);
        out[n * 300 + t] = s;
    }
}

// ---------------------------------------------------------------------------
extern "C" void kernel_launch(void* const* d_in, const int* in_sizes, int n_in,
                              void* d_out, int out_size) {
    (void)in_sizes; (void)n_in; (void)out_size;
    const float* s_in = (const float*)d_in[0];
    const float* W1   = (const float*)d_in[1];
    const float* W2   = (const float*)d_in[2];
    const float* Wf1  = (const float*)d_in[3];
    const float* Wf2  = (const float*)d_in[4];
    float* out = (float*)d_out;

    pool0_transpose_kernel<<<dim3(10, 512), dim3(32, 8)>>>(s_in);
    scan_s0_kernel<<<64, 256>>>();
    conv1_scan_kernel<<<dim3(32, 8), 256>>>(W1);
    pool1_scan_kernel<<<128, 256>>>();
    conv2_scan_kernel<<<dim3(16, 8), 128>>>(W2);
    pool2_scan_kernel<<<64, 256>>>();
    fc1_gemm_kernel<<<dim3(19, 8), 256>>>(Wf1);
    scan_u5_kernel<<<16, 256>>>();
    fc2_kernel<<<104, 256>>>(Wf2);
    final_scan_kernel<<<1, 128>>>(out);
}

// round 3
// speedup vs baseline: 2.0178x; 2.0178x over previous
#include <cuda_runtime.h>

// ---------------------------------------------------------------------------
// SLAYER SRM-alpha SNN forward, t-major layout [t*N + n].
// R2: pools fused into conv epilogues (g_s1/g_s3 eliminated), cp.async
// double-buffered input staging in convs, vectorized fc1 GEMM w/ prefetch.
// ---------------------------------------------------------------------------

#define T_STEPS 300

__device__ float g_s0[16384 * T_STEPS];   // pool0 potentials -> spikes (B,2,32,32)
__device__ float g_s2[32768 * T_STEPS];   // pool1 spikes (B,16,16,16)
__device__ float g_s4[16384 * T_STEPS];   // pool2 spikes (B,32,8,8)
__device__ float g_u5[4096  * T_STEPS];   // fc1 potentials -> spikes in place
__device__ float g_u6[88    * T_STEPS];   // fc2 potentials

struct Srm { float p1, q1, p2, q2; };

__device__ __forceinline__ float srm_step(Srm& s, float u) {
    const float D  = 0.36787944117144233f;   // exp(-1)
    const float CE = 2.7182818284590452f;    // e
    const float CR = -54.365636569180905f;   // -2*theta*e
    s.q1 = __fmul_rn(D, __fadd_rn(s.q1, s.p1));
    s.p1 = __fadd_rn(__fmul_rn(D, s.p1), u);
    float y = __fmul_rn(CE, s.q1);
    s.q2 = __fmul_rn(D, __fadd_rn(s.q2, s.p2));
    float sp = (__fadd_rn(y, __fmul_rn(CR, s.q2)) >= 10.0f) ? 1.0f : 0.0f;
    s.p2 = __fadd_rn(__fmul_rn(D, s.p2), sp);
    return sp;
}

__device__ __forceinline__ void cp_async4(void* sm, const void* gm) {
    unsigned s = (unsigned)__cvta_generic_to_shared(sm);
    asm volatile("cp.async.ca.shared.global [%0], [%1], 4;" :: "r"(s), "l"(gm));
}
__device__ __forceinline__ void cp_commit() { asm volatile("cp.async.commit_group;"); }
__device__ __forceinline__ void cp_wait0()  { asm volatile("cp.async.wait_group 0;" ::: "memory"); }

// ---------------------------------------------------------------------------
// K0: 4x4 sum-pool (gain 11) + transpose (B,2,128,128,T) -> t-major g_s0.
// ---------------------------------------------------------------------------
__global__ void pool0_transpose_kernel(const float* __restrict__ x) {
    __shared__ float sm[32][33];
    const int tx = threadIdx.x, ty = threadIdx.y;
    const int tb = blockIdx.x, nb = blockIdx.y;
    const int t  = tb * 32 + tx;
    const int ho = nb & 31;
    const int bc = nb >> 5;
    for (int j = ty; j < 32; j += 8) {
        float acc = 0.f;
        if (t < T_STEPS) {
            #pragma unroll
            for (int dy = 0; dy < 4; ++dy) {
                int h = ho * 4 + dy;
                const float* rowp = x + ((bc * 128 + h) * 128 + j * 4) * T_STEPS + t;
                acc += rowp[0] + rowp[300] + rowp[600] + rowp[900];
            }
        }
        sm[j][tx] = 11.0f * acc;
    }
    __syncthreads();
    for (int jj = ty; jj < 32; jj += 8) {
        int t2 = tb * 32 + jj;
        if (t2 < T_STEPS)
            g_s0[t2 * 16384 + nb * 32 + tx] = sm[tx][jj];
    }
}

// ---- generic in-place psp+spike scan ---------------------------------------
__device__ __forceinline__ void scan_body(float* buf, int N) {
    int n = blockIdx.x * blockDim.x + threadIdx.x;
    if (n >= N) return;
    Srm st = {0.f, 0.f, 0.f, 0.f};
    #pragma unroll 1
    for (int t = 0; t < T_STEPS; ++t) {
        float u = buf[t * N + n];
        buf[t * N + n] = srm_step(st, u);
    }
}
__global__ void scan_s0_kernel() { scan_body(g_s0, 16384); }
__global__ void scan_u5_kernel() { scan_body(g_u5, 4096); }

// ---------------------------------------------------------------------------
// conv1 (5x5,pad2,2->16) + psp + spike + 2x2 pool + psp + spike, fused.
// grid (hp=16, b=8), 256 thr: thread=(co 0..15, xp 0..15) owns the 2y x 2x
// conv quad feeding pooled neuron (co,hp,xp). cp.async double buffer.
// ---------------------------------------------------------------------------
__global__ void __launch_bounds__(256) conv1_fused_kernel(const float* __restrict__ W1) {
    __shared__ float sbuf[2][432];        // [buf][ci*216 + r*36 + c], rows 2hp-2..2hp+3
    const int tid = threadIdx.x;
    const int xp  = tid & 15;
    const int co  = tid >> 4;
    const int hp  = blockIdx.x;
    const int b   = blockIdx.y;
    float w[50];
    #pragma unroll
    for (int k = 0; k < 50; ++k) w[k] = W1[co * 50 + k];
    for (int i = tid; i < 864; i += 256) ((float*)sbuf)[i] = 0.f;  // OOB stays 0
    __syncthreads();

    const int inBase = b * 2048;
    // prologue: stage frame 0
    {
        const float* fr = g_s0 + inBase;
        for (int i = tid; i < 432; i += 256) {
            int ci = i / 216, rem = i - ci * 216, r = rem / 36, c = rem - r * 36;
            int row = 2 * hp + r - 2, col = c - 2;
            if (row >= 0 && row < 32 && col >= 0 && col < 32)
                cp_async4(&sbuf[0][i], fr + ci * 1024 + row * 32 + col);
        }
        cp_commit(); cp_wait0();
    }
    __syncthreads();

    Srm c00 = {0,0,0,0}, c01 = {0,0,0,0}, c10 = {0,0,0,0}, c11 = {0,0,0,0}, pl = {0,0,0,0};
    const int outIdx = ((b * 16 + co) * 16 + hp) * 16 + xp;

    #pragma unroll 1
    for (int t = 0; t < T_STEPS; ++t) {
        const int cur = t & 1;
        if (t + 1 < T_STEPS) {
            const float* fr = g_s0 + (t + 1) * 16384 + inBase;
            for (int i = tid; i < 432; i += 256) {
                int ci = i / 216, rem = i - ci * 216, r = rem / 36, c = rem - r * 36;
                int row = 2 * hp + r - 2, col = c - 2;
                if (row >= 0 && row < 32 && col >= 0 && col < 32)
                    cp_async4(&sbuf[cur ^ 1][i], fr + ci * 1024 + row * 32 + col);
            }
        }
        cp_commit();

        float a00 = 0.f, a01 = 0.f, a10 = 0.f, a11 = 0.f;
        #pragma unroll
        for (int ci = 0; ci < 2; ++ci) {
            const float* sp_ = &sbuf[cur][ci * 216 + 2 * xp];
            #pragma unroll
            for (int r = 0; r < 6; ++r) {
                float2 p0 = *(const float2*)(sp_ + r * 36);
                float2 p1 = *(const float2*)(sp_ + r * 36 + 2);
                float2 p2 = *(const float2*)(sp_ + r * 36 + 4);
                float v[6] = {p0.x, p0.y, p1.x, p1.y, p2.x, p2.y};
                if (r < 5) {                       // y0: ky = r
                    const int kb = ci * 25 + r * 5;
                    #pragma unroll
                    for (int kx = 0; kx < 5; ++kx) {
                        a00 = fmaf(v[kx],     w[kb + kx], a00);
                        a01 = fmaf(v[kx + 1], w[kb + kx], a01);
                    }
                }
                if (r >= 1) {                      // y1: ky = r-1
                    const int kb = ci * 25 + (r - 1) * 5;
                    #pragma unroll
                    for (int kx = 0; kx < 5; ++kx) {
                        a10 = fmaf(v[kx],     w[kb + kx], a10);
                        a11 = fmaf(v[kx + 1], w[kb + kx], a11);
                    }
                }
            }
        }
        float s00 = srm_step(c00, a00), s01 = srm_step(c01, a01);
        float s10 = srm_step(c10, a10), s11 = srm_step(c11, a11);
        float u = 11.0f * ((s00 + s01) + (s10 + s11));
        g_s2[t * 32768 + outIdx] = srm_step(pl, u);

        cp_wait0();
        __syncthreads();
    }
}

// ---------------------------------------------------------------------------
// conv2 (3x3,pad1,16->32) + psp + spike + 2x2 pool + psp + spike, fused.
// grid (hp=8, b=8, xh=2), 128 thr: thread=(co 0..31, xp 0..3) owns the 2y x 2x
// conv quad feeding pooled neuron (co,hp,xh*4+xp).
// ---------------------------------------------------------------------------
__global__ void __launch_bounds__(128) conv2_fused_kernel(const float* __restrict__ W2) {
    __shared__ float sbuf[2][640];        // [buf][ci*40 + r*10 + c], rows 2hp-1..2hp+2
    const int tid = threadIdx.x;
    const int xp  = tid & 3;
    const int co  = tid >> 2;
    const int hp  = blockIdx.x;           // 0..7
    const int b   = blockIdx.y;
    const int xh  = blockIdx.z;           // 0..1
    float w[144];
    #pragma unroll
    for (int k = 0; k < 144; ++k) w[k] = W2[co * 144 + k];
    for (int i = tid; i < 1280; i += 128) ((float*)sbuf)[i] = 0.f;
    __syncthreads();

    const int inBase = b * 4096;          // b*16ch*256px
    {
        const float* fr = g_s2 + inBase;
        for (int i = tid; i < 640; i += 128) {
            int ci = i / 40, rem = i - ci * 40, r = rem / 10, c = rem - r * 10;
            int row = 2 * hp + r - 1, col = xh * 8 + c - 1;
            if (row >= 0 && row < 16 && col >= 0 && col < 16)
                cp_async4(&sbuf[0][i], fr + ci * 256 + row * 16 + col);
        }
        cp_commit(); cp_wait0();
    }
    __syncthreads();

    Srm c00 = {0,0,0,0}, c01 = {0,0,0,0}, c10 = {0,0,0,0}, c11 = {0,0,0,0}, pl = {0,0,0,0};
    const int outIdx = ((b * 32 + co) * 8 + hp) * 8 + xh * 4 + xp;

    #pragma unroll 1
    for (int t = 0; t < T_STEPS; ++t) {
        const int cur = t & 1;
        if (t + 1 < T_STEPS) {
            const float* fr = g_s2 + (t + 1) * 32768 + inBase;
            for (int i = tid; i < 640; i += 128) {
                int ci = i / 40, rem = i - ci * 40, r = rem / 10, c = rem - r * 10;
                int row = 2 * hp + r - 1, col = xh * 8 + c - 1;
                if (row >= 0 && row < 16 && col >= 0 && col < 16)
                    cp_async4(&sbuf[cur ^ 1][i], fr + ci * 256 + row * 16 + col);
            }
        }
        cp_commit();

        float a00 = 0.f, a01 = 0.f, a10 = 0.f, a11 = 0.f;
        #pragma unroll
        for (int ci = 0; ci < 16; ++ci) {
            const float* sp_ = &sbuf[cur][ci * 40 + 2 * xp];
            #pragma unroll
            for (int r = 0; r < 4; ++r) {
                float2 p0 = *(const float2*)(sp_ + r * 10);
                float2 p1 = *(const float2*)(sp_ + r * 10 + 2);
                float v[4] = {p0.x, p0.y, p1.x, p1.y};
                if (r < 3) {                       // y0: ky = r
                    const int kb = ci * 9 + r * 3;
                    #pragma unroll
                    for (int kx = 0; kx < 3; ++kx) {
                        a00 = fmaf(v[kx],     w[kb + kx], a00);
                        a01 = fmaf(v[kx + 1], w[kb + kx], a01);
                    }
                }
                if (r >= 1) {                      // y1: ky = r-1
                    const int kb = ci * 9 + (r - 1) * 3;
                    #pragma unroll
                    for (int kx = 0; kx < 3; ++kx) {
                        a10 = fmaf(v[kx],     w[kb + kx], a10);
                        a11 = fmaf(v[kx + 1], w[kb + kx], a11);
                    }
                }
            }
        }
        float s00 = srm_step(c00, a00), s01 = srm_step(c01, a01);
        float s10 = srm_step(c10, a10), s11 = srm_step(c11, a11);
        float u = 11.0f * ((s00 + s01) + (s10 + s11));
        g_s4[t * 16384 + outIdx] = srm_step(pl, u);

        cp_wait0();
        __syncthreads();
    }
}

// ---------------------------------------------------------------------------
// fc1 GEMM: rows=(t,b) 2400, K=2048, N=512. 128x64 tile, 8x4 micro, kc=32,
// register double-buffered global loads, LDS.128 inner loop.
// ---------------------------------------------------------------------------
__global__ void __launch_bounds__(256) fc1_gemm_kernel(const float* __restrict__ Wf1) {
    __shared__ float As[32 * 132];
    __shared__ float Bs[32 * 68];
    const int tid = threadIdx.x;
    const int txn = tid & 15, tym = tid >> 4;
    const int m0 = blockIdx.x * 128, n0 = blockIdx.y * 64;
    float acc[8][4];
    #pragma unroll
    for (int i = 0; i < 8; ++i)
        #pragma unroll
        for (int j = 0; j < 4; ++j) acc[i][j] = 0.f;

    float4 ra[4], rb[2];
    #pragma unroll
    for (int e = 0; e < 4; ++e) {
        int i = tid + e * 256, m = i >> 3, kq = i & 7, row = m0 + m;
        ra[e] = (row < 2400) ? *(const float4*)(g_s4 + row * 2048 + kq * 4)
                             : make_float4(0.f, 0.f, 0.f, 0.f);
    }
    #pragma unroll
    for (int e = 0; e < 2; ++e) {
        int i = tid + e * 256, nn = i >> 3, kq = i & 7;
        rb[e] = *(const float4*)(Wf1 + (n0 + nn) * 2048 + kq * 4);
    }

    for (int kb = 0; kb < 2048; kb += 32) {
        #pragma unroll
        for (int e = 0; e < 4; ++e) {
            int i = tid + e * 256, m = i >> 3, kq = i & 7;
            As[(kq * 4 + 0) * 132 + m] = ra[e].x;
            As[(kq * 4 + 1) * 132 + m] = ra[e].y;
            As[(kq * 4 + 2) * 132 + m] = ra[e].z;
            As[(kq * 4 + 3) * 132 + m] = ra[e].w;
        }
        #pragma unroll
        for (int e = 0; e < 2; ++e) {
            int i = tid + e * 256, nn = i >> 3, kq = i & 7;
            Bs[(kq * 4 + 0) * 68 + nn] = rb[e].x;
            Bs[(kq * 4 + 1) * 68 + nn] = rb[e].y;
            Bs[(kq * 4 + 2) * 68 + nn] = rb[e].z;
            Bs[(kq * 4 + 3) * 68 + nn] = rb[e].w;
        }
        __syncthreads();
        if (kb + 32 < 2048) {
            #pragma unroll
            for (int e = 0; e < 4; ++e) {
                int i = tid + e * 256, m = i >> 3, kq = i & 7, row = m0 + m;
                ra[e] = (row < 2400) ? *(const float4*)(g_s4 + row * 2048 + kb + 32 + kq * 4)
                                     : make_float4(0.f, 0.f, 0.f, 0.f);
            }
            #pragma unroll
            for (int e = 0; e < 2; ++e) {
                int i = tid + e * 256, nn = i >> 3, kq = i & 7;
                rb[e] = *(const float4*)(Wf1 + (n0 + nn) * 2048 + kb + 32 + kq * 4);
            }
        }
        #pragma unroll
        for (int k = 0; k < 32; ++k) {
            float4 a0 = *(const float4*)&As[k * 132 + tym * 8];
            float4 a1 = *(const float4*)&As[k * 132 + tym * 8 + 4];
            float4 bq = *(const float4*)&Bs[k * 68 + txn * 4];
            float av[8] = {a0.x, a0.y, a0.z, a0.w, a1.x, a1.y, a1.z, a1.w};
            float bv[4] = {bq.x, bq.y, bq.z, bq.w};
            #pragma unroll
            for (int i = 0; i < 8; ++i)
                #pragma unroll
                for (int j = 0; j < 4; ++j)
                    acc[i][j] = fmaf(av[i], bv[j], acc[i][j]);
        }
        __syncthreads();
    }
    #pragma unroll
    for (int i = 0; i < 8; ++i) {
        int row = m0 + tym * 8 + i;
        if (row < 2400) {
            float4 v = make_float4(acc[i][0], acc[i][1], acc[i][2], acc[i][3]);
            *(float4*)(g_u5 + row * 512 + n0 + txn * 4) = v;
        }
    }
}

// ---------------------------------------------------------------------------
__global__ void fc2_kernel(const float* __restrict__ Wf2) {
    int idx = blockIdx.x * 256 + threadIdx.x;
    if (idx >= 2400 * 11) return;
    int row = idx / 11, o = idx % 11;
    const float* a  = g_u5 + row * 512;
    const float* wv = Wf2 + o * 512;
    float acc = 0.f;
    #pragma unroll 8
    for (int c = 0; c < 512; ++c) acc = fmaf(a[c], wv[c], acc);
    g_u6[idx] = acc;
}

__global__ void final_scan_kernel(float* __restrict__ out) {
    int n = threadIdx.x;
    if (n >= 88) return;
    Srm st = {0.f, 0.f, 0.f, 0.f};
    #pragma unroll 1
    for (int t = 0; t < T_STEPS; ++t) {
        float s = srm_step(st, g_u6[t * 88 + n]);
        out[n * 300 + t] = s;
    }
}

// ---------------------------------------------------------------------------
extern "C" void kernel_launch(void* const* d_in, const int* in_sizes, int n_in,
                              void* d_out, int out_size) {
    (void)in_sizes; (void)n_in; (void)out_size;
    const float* s_in = (const float*)d_in[0];
    const float* W1   = (const float*)d_in[1];
    const float* W2   = (const float*)d_in[2];
    const float* Wf1  = (const float*)d_in[3];
    const float* Wf2  = (const float*)d_in[4];
    float* out = (float*)d_out;

    pool0_transpose_kernel<<<dim3(10, 512), dim3(32, 8)>>>(s_in);
    scan_s0_kernel<<<64, 256>>>();
    conv1_fused_kernel<<<dim3(16, 8), 256>>>(W1);
    conv2_fused_kernel<<<dim3(8, 8, 2), 128>>>(W2);
    fc1_gemm_kernel<<<dim3(19, 8), 256>>>(Wf1);
    scan_u5_kernel<<<16, 256>>>();
    fc2_kernel<<<104, 256>>>(Wf2);
    final_scan_kernel<<<1, 128>>>(out);
}